// round 2
// baseline (speedup 1.0000x reference)
#include <cuda_runtime.h>

// Problem constants
#define NB 8
#define EDIM 256
#define HH 32
#define WW 32
#define NE 16384
#define M_TOK (NB * HH * WW)   // 8192 tokens

// GEMM tiling
#define BM 64
#define BN 128
#define BK 16
#define NTHR 128
#define BN_PAD 132   // +4 floats: breaks 16-way STS bank conflict, keeps 16B row alignment

__device__ float g_cnorm[NE];
__device__ int   g_idx[M_TOK];

// ---------------------------------------------------------------------------
// Kernel 1: codebook row norms  |c|^2
// 8 rows per 256-thread block, 32 lanes per row
// ---------------------------------------------------------------------------
__global__ void cnorm_kernel(const float* __restrict__ cb) {
    int row  = blockIdx.x * 8 + (threadIdx.x >> 5);
    int lane = threadIdx.x & 31;
    const float* r = cb + row * EDIM;
    float s = 0.f;
#pragma unroll
    for (int i = lane; i < EDIM; i += 32) {
        float v = r[i];
        s += v * v;
    }
#pragma unroll
    for (int o = 16; o > 0; o >>= 1) s += __shfl_down_sync(0xffffffffu, s, o);
    if (lane == 0) g_cnorm[row] = s;
}

// ---------------------------------------------------------------------------
// Kernel 2: fused distance-GEMM + per-token argmin
//   score[t][n] = |c_n|^2 - 2 * dot(x_t, c_n)      (|x|^2 irrelevant to argmin)
// CTA: 64 tokens x (loop over all 16384 codes in 128-wide tiles)
// 128 threads, 8x8 register micro-tile, BK=16 smem staging, register prefetch.
// ---------------------------------------------------------------------------
__global__ void __launch_bounds__(NTHR, 1)
vq_argmin_kernel(const float* __restrict__ z, const float* __restrict__ cb) {
    __shared__ float As[BK][BM];        // 4 KB   As[k][m]
    __shared__ float Bs[BK][BN_PAD];    // 8.25KB Bs[k][n]
    __shared__ float cns[BN];
    __shared__ float rv[BM][16];
    __shared__ int   ri[BM][16];

    const int tx = threadIdx.x;
    const int rt = tx >> 4;   // 0..7  : row-thread   (8 rows each)
    const int ct = tx & 15;   // 0..15 : col-thread   (8 cols each)

    const int t0 = blockIdx.x * BM;
    const int b  = t0 >> 10;          // 64 | 1024, so tile stays in one batch plane
    const int p0 = t0 & 1023;
    // x_t[e] = z[b, e, p]  ->  zb[e*1024 + m]
    const float* zb = z + (size_t)b * (EDIM * HH * WW) + p0;

    // A-load mapping: thread -> (m = tx&63, kk = tx>>6 stepping by 2)
    const int a_m   = tx & 63;
    const int a_kk0 = tx >> 6;              // 0..1
    // B-load mapping: thread -> (kk = tx&15, nsub = tx>>4, 16 n's stride 8)
    const int b_kk   = tx & 15;
    const int b_nsub = tx >> 4;             // 0..7

    float best_val[8];
    int   best_idx[8];
#pragma unroll
    for (int i = 0; i < 8; ++i) { best_val[i] = 3.4e38f; best_idx[i] = 0; }

    float a_pf[8];
    float b_pf[16];

    for (int n0 = 0; n0 < NE; n0 += BN) {
        __syncthreads();                      // protect cns/smem from prev readers
        cns[tx] = g_cnorm[n0 + tx];

        float acc[8][8];
#pragma unroll
        for (int i = 0; i < 8; ++i)
#pragma unroll
            for (int j = 0; j < 8; ++j) acc[i][j] = 0.f;

        // ---- preload k-tile 0 into registers ----
        {
            const int k0 = 0;
#pragma unroll
            for (int u = 0; u < 8; ++u) {
                int kk = a_kk0 + 2 * u;
                a_pf[u] = zb[(k0 + kk) * 1024 + a_m];
            }
#pragma unroll
            for (int j = 0; j < 16; ++j) {
                int n = b_nsub + j * 8;
                b_pf[j] = cb[(size_t)(n0 + n) * EDIM + k0 + b_kk];
            }
        }

#pragma unroll 1
        for (int kt = 0; kt < EDIM / BK; ++kt) {
            __syncthreads();
            // regs -> smem
#pragma unroll
            for (int u = 0; u < 8; ++u) As[a_kk0 + 2 * u][a_m] = a_pf[u];
#pragma unroll
            for (int j = 0; j < 16; ++j) Bs[b_kk][b_nsub + j * 8] = b_pf[j];
            __syncthreads();

            // prefetch next k-tile while computing
            if (kt + 1 < EDIM / BK) {
                const int k0 = (kt + 1) * BK;
#pragma unroll
                for (int u = 0; u < 8; ++u) {
                    int kk = a_kk0 + 2 * u;
                    a_pf[u] = zb[(k0 + kk) * 1024 + a_m];
                }
#pragma unroll
                for (int j = 0; j < 16; ++j) {
                    int n = b_nsub + j * 8;
                    b_pf[j] = cb[(size_t)(n0 + n) * EDIM + k0 + b_kk];
                }
            }

#pragma unroll
            for (int k = 0; k < BK; ++k) {
                float a[8], bb[8];
                float4 av0 = *(const float4*)&As[k][rt * 8];
                float4 av1 = *(const float4*)&As[k][rt * 8 + 4];
                float4 bv0 = *(const float4*)&Bs[k][ct * 8];
                float4 bv1 = *(const float4*)&Bs[k][ct * 8 + 4];
                a[0]=av0.x; a[1]=av0.y; a[2]=av0.z; a[3]=av0.w;
                a[4]=av1.x; a[5]=av1.y; a[6]=av1.z; a[7]=av1.w;
                bb[0]=bv0.x; bb[1]=bv0.y; bb[2]=bv0.z; bb[3]=bv0.w;
                bb[4]=bv1.x; bb[5]=bv1.y; bb[6]=bv1.z; bb[7]=bv1.w;
#pragma unroll
                for (int i = 0; i < 8; ++i)
#pragma unroll
                    for (int j = 0; j < 8; ++j)
                        acc[i][j] += a[i] * bb[j];
            }
        }

        // score + running argmin (n ascending within thread; strict < keeps first)
#pragma unroll
        for (int j = 0; j < 8; ++j) {
            int   n  = n0 + ct * 8 + j;
            float cn = cns[ct * 8 + j];
#pragma unroll
            for (int i = 0; i < 8; ++i) {
                float s = fmaf(-2.f, acc[i][j], cn);
                if (s < best_val[i]) { best_val[i] = s; best_idx[i] = n; }
            }
        }
    }

    // cross-thread reduction per token row (prefer smaller index on tie)
    __syncthreads();
#pragma unroll
    for (int i = 0; i < 8; ++i) {
        rv[rt * 8 + i][ct] = best_val[i];
        ri[rt * 8 + i][ct] = best_idx[i];
    }
    __syncthreads();
    if (tx < BM) {
        float bv = rv[tx][0];
        int   bi = ri[tx][0];
#pragma unroll
        for (int c = 1; c < 16; ++c) {
            float v  = rv[tx][c];
            int   id = ri[tx][c];
            if (v < bv || (v == bv && id < bi)) { bv = v; bi = id; }
        }
        g_idx[t0 + tx] = bi;
    }
}

// ---------------------------------------------------------------------------
// Kernel 3: gather  out[b,e,h,w] = codebook[idx[b,h,w], e]
// Block per (b,h); lanes map to w -> fully coalesced 128B writes.
// ---------------------------------------------------------------------------
__global__ void gather_kernel(const float* __restrict__ cb, float* __restrict__ out) {
    int bh = blockIdx.x;               // 0..255
    int b  = bh >> 5;
    int h  = bh & 31;
    int w  = threadIdx.x & 31;
    int e0 = threadIdx.x >> 5;         // 0..7

    int t   = b * 1024 + h * 32 + w;
    int idx = g_idx[t];
    const float* row = cb + (size_t)idx * EDIM;
    float* ob = out + (size_t)b * (EDIM * 1024) + h * 32 + w;

#pragma unroll
    for (int e = e0; e < EDIM; e += 8)
        ob[e * 1024] = row[e];
}

// ---------------------------------------------------------------------------
extern "C" void kernel_launch(void* const* d_in, const int* in_sizes, int n_in,
                              void* d_out, int out_size) {
    const float* z  = (const float*)d_in[0];   // [8,256,32,32]
    const float* cb = (const float*)d_in[1];   // [16384,256]
    float* out = (float*)d_out;                // [8,256,32,32]

    cnorm_kernel<<<NE / 8, 256>>>(cb);
    vq_argmin_kernel<<<M_TOK / BM, NTHR>>>(z, cb);
    gather_kernel<<<NB * HH, 256>>>(cb, out);
}

// round 4
// speedup vs baseline: 7.1598x; 7.1598x over previous
#include <cuda_runtime.h>
#include <cuda_bf16.h>
#include <cstdint>

#define NE 16384
#define M_TOK 8192
#define NTILE 64          // N-tiles per CTA (half codebook / 128)

__device__ __align__(1024) __nv_bfloat16 g_Xb[M_TOK * 256];
__device__ __align__(1024) float         g_Xf[M_TOK * 256];
__device__ __align__(1024) __nv_bfloat16 g_Cb[NE * 256];
__device__ __align__(16)   float g_cnorm[NE];
__device__ int g_cand[M_TOK * 64];
__device__ int g_idx[M_TOK];

static __device__ __forceinline__ uint32_t s2u(const void* p) {
    uint32_t a;
    asm("{ .reg .u64 t; cvta.to.shared.u64 t, %1; cvt.u32.u64 %0, t; }" : "=r"(a) : "l"(p));
    return a;
}
#define CPA16(s, g) asm volatile("cp.async.cg.shared.global [%0], [%1], 16;" :: "r"(s), "l"(g) : "memory")
#define CPC()  asm volatile("cp.async.commit_group;" ::: "memory")
#define CPW1() asm volatile("cp.async.wait_group 1;" ::: "memory")
#define CPW0() asm volatile("cp.async.wait_group 0;" ::: "memory")

static __device__ __forceinline__ void ldsm4(uint32_t& r0, uint32_t& r1, uint32_t& r2,
                                             uint32_t& r3, uint32_t a) {
    asm volatile("ldmatrix.sync.aligned.m8n8.x4.shared.b16 {%0,%1,%2,%3}, [%4];"
                 : "=r"(r0), "=r"(r1), "=r"(r2), "=r"(r3) : "r"(a));
}
static __device__ __forceinline__ void mma16816(float& d0, float& d1, float& d2, float& d3,
                                                uint32_t a0, uint32_t a1, uint32_t a2,
                                                uint32_t a3, uint32_t b0, uint32_t b1) {
    asm volatile("mma.sync.aligned.m16n8k16.row.col.f32.bf16.bf16.f32 "
                 "{%0,%1,%2,%3}, {%4,%5,%6,%7}, {%8,%9}, {%0,%1,%2,%3};"
                 : "+f"(d0), "+f"(d1), "+f"(d2), "+f"(d3)
                 : "r"(a0), "r"(a1), "r"(a2), "r"(a3), "r"(b0), "r"(b1));
}

// ---------------- prep: transpose z -> token-major fp32 + bf16 --------------
__global__ void conv_z_kernel(const float* __restrict__ z) {
    __shared__ float tile[32][33];
    int b = blockIdx.z, e0 = blockIdx.y * 32, p0 = blockIdx.x * 32;
    int tx = threadIdx.x, ty = threadIdx.y;
    const float* zb = z + (size_t)b * 256 * 1024;
#pragma unroll
    for (int r = 0; r < 4; r++)
        tile[ty + 8 * r][tx] = zb[(size_t)(e0 + ty + 8 * r) * 1024 + p0 + tx];
    __syncthreads();
#pragma unroll
    for (int r = 0; r < 4; r++) {
        int p = p0 + ty + 8 * r, e = e0 + tx;
        float v = tile[tx][ty + 8 * r];
        size_t o = (size_t)(b * 1024 + p) * 256 + e;
        g_Xf[o] = v;
        g_Xb[o] = __float2bfloat16(v);
    }
}

// ---------------- prep: codebook -> bf16 + |c|^2 -----------------------------
__global__ void conv_cb_kernel(const float* __restrict__ cb) {
    int row = blockIdx.x * 8 + (threadIdx.x >> 5);
    int lane = threadIdx.x & 31;
    const float* r = cb + (size_t)row * 256;
    float s = 0.f;
#pragma unroll
    for (int i = 0; i < 8; i++) {
        float v = r[lane + 32 * i];
        s += v * v;
        g_Cb[(size_t)row * 256 + lane + 32 * i] = __float2bfloat16(v);
    }
#pragma unroll
    for (int o = 16; o > 0; o >>= 1) s += __shfl_down_sync(0xffffffffu, s, o);
    if (lane == 0) g_cnorm[row] = s;
}

// ---------------- main GEMM: mma.sync bf16, top-2/slice shortlist ------------
// smem: cns[2][128] f32 @0 (1024B), A @1024 (128 x 528B), B[2] @68608 (2 x 128 x 528B)
#define SM_CN 0
#define SM_A  1024
#define SM_B  68608
#define SMEMT (68608 + 2 * 67584)   // 203776

__global__ void __launch_bounds__(256, 1) vq_gemm_kernel() {
    extern __shared__ char smem[];
    const uint32_t sb = s2u(smem);
    const int tid  = threadIdx.x;
    const int lane = tid & 31;
    const int wid  = tid >> 5;
    const int wm   = wid >> 2;           // 0..1  (64-row block)
    const int wn   = wid & 3;            // 0..3  (32-col block)
    const int m0   = (blockIdx.x >> 1) * 128;
    const int half = blockIdx.x & 1;
    const int nb0  = half * (NE / 2);

    const char* gA = (const char*)g_Xb + (size_t)m0 * 512;
    const char* gB = (const char*)g_Cb + (size_t)nb0 * 512;
    const char* gC = (const char*)(g_cnorm + nb0);

    // cp.async chunk mapping: c = (tid&31)*16 bytes, rows (tid>>5) + 8i
    const int c16  = (tid & 31) * 16;
    const int row0 = tid >> 5;

    // ---- prologue: A + B0 + cns0 (group0), B1 + cns1 (group1) ----
#pragma unroll
    for (int i = 0; i < 16; i++) {
        int r = row0 + 8 * i;
        CPA16(sb + SM_A + r * 528 + c16, gA + r * 512 + c16);
    }
#pragma unroll
    for (int i = 0; i < 16; i++) {
        int r = row0 + 8 * i;
        CPA16(sb + SM_B + r * 528 + c16, gB + r * 512 + c16);
    }
    if (tid < 32) CPA16(sb + SM_CN + tid * 16, gC + tid * 16);
    CPC();
#pragma unroll
    for (int i = 0; i < 16; i++) {
        int r = row0 + 8 * i;
        CPA16(sb + SM_B + 67584 + r * 528 + c16, gB + 65536 + r * 512 + c16);
    }
    if (tid < 32) CPA16(sb + SM_CN + 512 + tid * 16, gC + 512 + tid * 16);
    CPC();

    // ldmatrix base addresses
    // A: row = wm*64 + mi*16 + (lane&15), kbyte = (lane>>4)*16 + ks*32
    uint32_t aBase[4];
#pragma unroll
    for (int mi = 0; mi < 4; mi++)
        aBase[mi] = sb + SM_A + (wm * 64 + mi * 16 + (lane & 15)) * 528 + (lane >> 4) * 16;
    // B: row = wn*32 + nb*16 + ((lane>>4)&1)*8 + (lane&7), kbyte = ((lane>>3)&1)*16 + ks*32
    const uint32_t bRowOff =
        (uint32_t)((wn * 32 + ((lane >> 4) & 1) * 8 + (lane & 7)) * 528 + ((lane >> 3) & 1) * 16);

    // top-2 shortlist per (thread, row-slot): 8 slots (mi*2 + hi)
    float tv0[8], tv1[8];
    int   ti0[8], ti1[8];
#pragma unroll
    for (int i = 0; i < 8; i++) { tv0[i] = 3.4e38f; tv1[i] = 3.4e38f; ti0[i] = 0; ti1[i] = 0; }

#pragma unroll 1
    for (int t = 0; t < NTILE; t++) {
        const int s = t & 1;
        if (t < NTILE - 1) CPW1(); else CPW0();
        __syncthreads();

        float acc[4][4][4];
#pragma unroll
        for (int mi = 0; mi < 4; mi++)
#pragma unroll
            for (int ni = 0; ni < 4; ni++)
#pragma unroll
                for (int q = 0; q < 4; q++) acc[mi][ni][q] = 0.f;

        const uint32_t bBuf = sb + SM_B + s * 67584 + bRowOff;
#pragma unroll
        for (int ks = 0; ks < 16; ks++) {
            uint32_t a[4][4];
#pragma unroll
            for (int mi = 0; mi < 4; mi++)
                ldsm4(a[mi][0], a[mi][1], a[mi][2], a[mi][3], aBase[mi] + ks * 32);
            uint32_t b[4][2];
#pragma unroll
            for (int nb = 0; nb < 2; nb++) {
                uint32_t r0, r1, r2, r3;
                ldsm4(r0, r1, r2, r3, bBuf + nb * (16 * 528) + ks * 32);
                b[nb * 2][0] = r0; b[nb * 2][1] = r1;
                b[nb * 2 + 1][0] = r2; b[nb * 2 + 1][1] = r3;
            }
#pragma unroll
            for (int mi = 0; mi < 4; mi++)
#pragma unroll
                for (int ni = 0; ni < 4; ni++)
                    mma16816(acc[mi][ni][0], acc[mi][ni][1], acc[mi][ni][2], acc[mi][ni][3],
                             a[mi][0], a[mi][1], a[mi][2], a[mi][3], b[ni][0], b[ni][1]);
        }

        // epilogue: score + top-2 update (ascending n, strict < keeps first)
        const float2* cns2 = (const float2*)(smem + SM_CN + s * 512);
        const int nbase = nb0 + t * 128;
#pragma unroll
        for (int ni = 0; ni < 4; ni++) {
            float2 cn = cns2[wn * 16 + ni * 4 + (lane & 3)];
            int ncol = nbase + wn * 32 + ni * 8 + (lane & 3) * 2;
#pragma unroll
            for (int mi = 0; mi < 4; mi++) {
#pragma unroll
                for (int hi = 0; hi < 2; hi++) {
                    const int sl = mi * 2 + hi;
                    float s0 = fmaf(-2.f, acc[mi][ni][hi * 2 + 0], cn.x);
                    float s1 = fmaf(-2.f, acc[mi][ni][hi * 2 + 1], cn.y);
                    if (s0 < tv1[sl]) {
                        if (s0 < tv0[sl]) { tv1[sl]=tv0[sl]; ti1[sl]=ti0[sl]; tv0[sl]=s0; ti0[sl]=ncol; }
                        else              { tv1[sl]=s0; ti1[sl]=ncol; }
                    }
                    if (s1 < tv1[sl]) {
                        if (s1 < tv0[sl]) { tv1[sl]=tv0[sl]; ti1[sl]=ti0[sl]; tv0[sl]=s1; ti0[sl]=ncol+1; }
                        else              { tv1[sl]=s1; ti1[sl]=ncol+1; }
                    }
                }
            }
        }

        __syncthreads();   // all warps done reading buffer s before refill
        if (t + 2 < NTILE) {
            const char* src = gB + (size_t)(t + 2) * 65536;
#pragma unroll
            for (int i = 0; i < 16; i++) {
                int r = row0 + 8 * i;
                CPA16(sb + SM_B + s * 67584 + r * 528 + c16, src + r * 512 + c16);
            }
            if (tid < 32)
                CPA16(sb + SM_CN + s * 512 + tid * 16, gC + (size_t)(t + 2) * 512 + tid * 16);
            CPC();
        } else {
            CPC();         // keep group counting uniform
        }
    }

    // write candidates: 16 slices/row/half x 2 entries
    const int slice = wn * 4 + (lane & 3);
#pragma unroll
    for (int mi = 0; mi < 4; mi++)
#pragma unroll
        for (int hi = 0; hi < 2; hi++) {
            int row = wm * 64 + mi * 16 + (lane >> 2) + hi * 8;
            int* oc = g_cand + (size_t)(m0 + row) * 64 + half * 32 + slice * 2;
            oc[0] = ti0[mi * 2 + hi];
            oc[1] = ti1[mi * 2 + hi];
        }
}

// ---------------- exact fp32 rescore of 64 candidates per token --------------
__global__ void rescore_kernel(const float* __restrict__ cb) {
    int t = blockIdx.x * 8 + (threadIdx.x >> 5);
    int lane = threadIdx.x & 31;
    const float* x = g_Xf + (size_t)t * 256;
    float xv[8];
#pragma unroll
    for (int i = 0; i < 8; i++) xv[i] = x[lane + 32 * i];
    float best = 3.4e38f;
    int bi = NE;
#pragma unroll 1
    for (int c = 0; c < 64; c++) {
        int n = g_cand[(size_t)t * 64 + c];
        const float* cr = cb + (size_t)n * 256;
        float d = 0.f;
#pragma unroll
        for (int i = 0; i < 8; i++) d = fmaf(xv[i], cr[lane + 32 * i], d);
#pragma unroll
        for (int o = 16; o > 0; o >>= 1) d += __shfl_xor_sync(0xffffffffu, d, o);
        float sc = fmaf(-2.f, d, g_cnorm[n]);
        if (sc < best || (sc == best && n < bi)) { best = sc; bi = n; }
    }
    if (lane == 0) g_idx[t] = bi;
}

// ---------------- gather: out[b,e,h,w] = cb[idx[b,h,w], e] -------------------
__global__ void gather_kernel(const float* __restrict__ cb, float* __restrict__ out) {
    int bh = blockIdx.x;
    int b = bh >> 5, h = bh & 31;
    int w = threadIdx.x & 31, e0 = threadIdx.x >> 5;
    int t = b * 1024 + h * 32 + w;
    int idx = g_idx[t];
    const float* row = cb + (size_t)idx * 256;
    float* ob = out + (size_t)b * (256 * 1024) + h * 32 + w;
#pragma unroll
    for (int e = e0; e < 256; e += 8) ob[e * 1024] = row[e];
}

extern "C" void kernel_launch(void* const* d_in, const int* in_sizes, int n_in,
                              void* d_out, int out_size) {
    const float* z  = (const float*)d_in[0];
    const float* cb = (const float*)d_in[1];
    float* out = (float*)d_out;

    static int cfg_done = 0;
    if (!cfg_done) {
        cudaFuncSetAttribute(vq_gemm_kernel, cudaFuncAttributeMaxDynamicSharedMemorySize, SMEMT);
        cfg_done = 1;
    }

    conv_z_kernel<<<dim3(32, 8, 8), dim3(32, 8)>>>(z);
    conv_cb_kernel<<<NE / 8, 256>>>(cb);
    vq_gemm_kernel<<<128, 256, SMEMT>>>();
    rescore_kernel<<<M_TOK / 8, 256>>>(cb);
    gather_kernel<<<256, 256>>>(cb, out);
}